// round 14
// baseline (speedup 1.0000x reference)
#include <cuda_runtime.h>
#include <math.h>

#define D     1024
#define SQ    1024          // sequence length
#define BB    4             // batch
#define NH    16            // heads
#define HDIM  64            // head dim
#define FFD   4096
#define NROWS 4096          // BB*SQ
#define EPSF  1e-7f
#define MAXT  0.99999f      // 1 - 1e-5 (as float)
#define WSZ   ((size_t)D*D) // 1M floats per D x D weight

// ---------------- scratch (static device memory; no runtime allocation) ----------------
__device__ __align__(16) float g_ada [BB*6*D];
__device__ __align__(16) float g_tm  [NROWS*D];
__device__ __align__(16) float g_lin3[(size_t)3*NROWS*D];
__device__ __align__(16) float g_qkvt[(size_t)3*NROWS*D];
__device__ __align__(16) float g_att [NROWS*D];
__device__ __align__(16) float g_tcat[NROWS*D];
__device__ __align__(16) float g_zb  [NROWS*D];
__device__ __align__(16) float g_xnew[NROWS*D];
__device__ __align__(16) float g_big [(size_t)NROWS*FFD];   // FFN hidden
__device__ __align__(16) float g_w   [(size_t)12*1024*1024]; // tf32-rounded, TRANSPOSED [N,K] weights

// ---------------- reduction helpers (blockDim == 256) ----------------
__device__ __forceinline__ float warp_sum(float v){
#pragma unroll
    for (int o=16;o;o>>=1) v += __shfl_xor_sync(0xffffffffu, v, o);
    return v;
}
__device__ __forceinline__ float blk_sum(float v, float* sb){
    int lane = threadIdx.x & 31, w = threadIdx.x >> 5;
    v = warp_sum(v);
    __syncthreads();
    if (lane == 0) sb[w] = v;
    __syncthreads();
    float r = 0.f;
#pragma unroll
    for (int i=0;i<8;i++) r += sb[i];
    return r;
}

// ---------------- tf32 helpers ----------------
__device__ __forceinline__ unsigned f2t(float f){
    unsigned u; asm("cvt.rna.tf32.f32 %0, %1;" : "=r"(u) : "f"(f)); return u;
}
__device__ __forceinline__ float rnd_t(float f){ return __uint_as_float(f2t(f)); }
__device__ __forceinline__ uint4 cvt4(float4 v){
    return make_uint4(f2t(v.x), f2t(v.y), f2t(v.z), f2t(v.w));
}
__device__ __forceinline__ void mma_tf32(float* d, const unsigned* a, const unsigned* b){
    asm volatile("mma.sync.aligned.m16n8k8.row.col.f32.tf32.tf32.f32 "
        "{%0,%1,%2,%3}, {%4,%5,%6,%7}, {%8,%9}, {%0,%1,%2,%3};"
        : "+f"(d[0]), "+f"(d[1]), "+f"(d[2]), "+f"(d[3])
        : "r"(a[0]), "r"(a[1]), "r"(a[2]), "r"(a[3]), "r"(b[0]), "r"(b[1]));
}
__device__ __forceinline__ void cp16(void* sp, const void* gp){
    unsigned sa = (unsigned)__cvta_generic_to_shared(sp);
    asm volatile("cp.async.cg.shared.global [%0], [%1], 16;" :: "r"(sa), "l"(gp));
}
// ldmatrix x4: lane l supplies a 16B row address; result reg i = matrix_i(gid, tg) as b32.
__device__ __forceinline__ void ldsm4(unsigned addr, unsigned &r0, unsigned &r1,
                                      unsigned &r2, unsigned &r3){
    asm volatile("ldmatrix.sync.aligned.m8n8.x4.shared.b16 {%0,%1,%2,%3}, [%4];"
        : "=r"(r0), "=r"(r1), "=r"(r2), "=r"(r3) : "r"(addr));
}

// ---------------- round weights to tf32 AND transpose to [N,K] ----------------
// in: [K,N] row-major; out: [N,K] row-major at fixed offsets in g_w.
__global__ __launch_bounds__(256) void k_transp(
    const float* __restrict__ s0, const float* __restrict__ s1,
    const float* __restrict__ s2, const float* __restrict__ s3,
    const float* __restrict__ s4, const float* __restrict__ s5,
    float* __restrict__ dst)
{
    __shared__ float t[32][33];
    const float* srcs[6] = {s0,s1,s2,s3,s4,s5};
    const int offs[6] = {0, 1<<20, 2<<20, 3<<20, 4<<20, 8<<20};
    const int Ks [6] = {1024,1024,1024,1024,1024,4096};
    const int Ns [6] = {1024,1024,1024,1024,4096,1024};
    int zi = blockIdx.z;
    int K = Ks[zi], N = Ns[zi];
    int k0 = blockIdx.y*32, n0 = blockIdx.x*32;
    if (k0 >= K || n0 >= N) return;
    const float* src = srcs[zi];
    float* d0 = dst + offs[zi];
    int tx = threadIdx.x & 31, ty = threadIdx.x >> 5;
    for (int i = ty; i < 32; i += 8)
        t[i][tx] = rnd_t(src[(size_t)(k0+i)*N + n0 + tx]);
    __syncthreads();
    for (int i = ty; i < 32; i += 8)
        d0[(size_t)(n0+i)*K + k0 + tx] = t[tx][i];
}

// ---------------- ada = t_emb @ w_ada + b_ada ----------------
__global__ __launch_bounds__(256) void k_ada(const float* __restrict__ temb,
                                             const float* __restrict__ w,
                                             const float* __restrict__ bias){
    __shared__ float ts[D];
    int b = blockIdx.y;
    int j = blockIdx.x * 256 + threadIdx.x;
    for (int i = threadIdx.x; i < D; i += 256) ts[i] = temb[b*D + i];
    __syncthreads();
    float acc = bias[j];
    const float* wp = w + j;
#pragma unroll 4
    for (int k = 0; k < D; k++) acc += ts[k] * wp[(size_t)k * (6*D)];
    g_ada[b*6*D + j] = acc;
}

// ---------------- logmap0 + layernorm + modulation + clipnorm (tf32-rounded out) ----------------
__global__ __launch_bounds__(256) void k_prep(const float* __restrict__ P,
                                              int sh_off, int sc_off,
                                              float* __restrict__ out){
    __shared__ float sb[8];
    const float LC = atanhf(MAXT);
    int row = blockIdx.x, b = row >> 10;
    int t = threadIdx.x;
    const float* xr = P + (size_t)row * D;
    float x0[4];
#pragma unroll
    for (int i=0;i<4;i++) x0[i] = xr[t + i*256];
    float ss = 0.f;
#pragma unroll
    for (int i=0;i<4;i++) ss += x0[i]*x0[i];
    ss = blk_sum(ss, sb);
    float n  = fmaxf(sqrtf(ss), EPSF);
    float a  = fminf(fmaxf(n, EPSF), MAXT);
    float ls = atanhf(a) / n;
    float u[4];
#pragma unroll
    for (int i=0;i<4;i++) u[i] = x0[i]*ls;
    float m = blk_sum(u[0]+u[1]+u[2]+u[3], sb) * (1.0f/D);
    float vv = 0.f;
#pragma unroll
    for (int i=0;i<4;i++){ float d0 = u[i]-m; vv += d0*d0; }
    vv = blk_sum(vv, sb) * (1.0f/D);
    float inv = rsqrtf(vv + 1e-6f);
    const float* ad = g_ada + b*6*D;
    float v[4]; float s2 = 0.f;
#pragma unroll
    for (int i=0;i<4;i++){
        int d0 = t + i*256;
        float xn  = (u[i]-m)*inv;
        float val = xn * (1.0f + ad[sc_off + d0]) + ad[sh_off + d0];
        v[i] = val; s2 += val*val;
    }
    s2 = blk_sum(s2, sb);
    float nv = fmaxf(sqrtf(s2), EPSF);
    float cl = fminf(nv, LC) / nv;
#pragma unroll
    for (int i=0;i<4;i++) out[(size_t)row*D + t + i*256] = rnd_t(v[i]*cl);
}

// ---------------- beta-split to heads (q/k/v via blockIdx.y) ----------------
__global__ __launch_bounds__(256) void k_heads(const float* __restrict__ lin3,
                                               float* __restrict__ qkvt, float Rf){
    __shared__ float sb[8];
    const float LC = atanhf(MAXT);
    int row = blockIdx.x, b = row >> 10, s = row & 1023;
    const float* lin = lin3 + (size_t)blockIdx.y*NROWS*D;
    float* out = qkvt + (size_t)blockIdx.y*NROWS*D;
    int t = threadIdx.x, h = t >> 4, c = (t & 15) * 4;
    float4 z = *(const float4*)(lin + (size_t)row*D + h*HDIM + c);
    float ss = z.x*z.x + z.y*z.y + z.z*z.z + z.w*z.w;
    float tot = blk_sum(ss, sb);
    float n  = fmaxf(sqrtf(tot), EPSF);
    float s1 = fminf(n, LC)/n * Rf;
    float tx = z.x*s1, ty = z.y*s1, tz = z.z*s1, tw = z.w*s1;
    float hs = tx*tx + ty*ty + tz*tz + tw*tw;
#pragma unroll
    for (int o=1;o<16;o<<=1) hs += __shfl_xor_sync(0xffffffffu, hs, o);
    float nh = fmaxf(sqrtf(hs), EPSF);
    float s2 = fminf(nh, LC)/nh;
    float4 o4 = make_float4(rnd_t(tx*s2), rnd_t(ty*s2), rnd_t(tz*s2), rnd_t(tw*s2));
    *(float4*)(out + ((size_t)(b*NH + h)*SQ + s)*HDIM + c) = o4;
}

// ---------------- merge heads (tf32-rounded out) ----------------
__global__ __launch_bounds__(256) void k_merge(const float* __restrict__ att,
                                               float* __restrict__ out, float Rinv){
    __shared__ float sb[8];
    const float LC = atanhf(MAXT);
    int row = blockIdx.x, b = row >> 10, s = row & 1023;
    int t = threadIdx.x, h = t >> 4, c = (t & 15) * 4;
    float4 z = *(const float4*)(att + ((size_t)(b*NH + h)*SQ + s)*HDIM + c);
    float hs = z.x*z.x + z.y*z.y + z.z*z.z + z.w*z.w;
#pragma unroll
    for (int o=1;o<16;o<<=1) hs += __shfl_xor_sync(0xffffffffu, hs, o);
    float nh = fmaxf(sqrtf(hs), EPSF);
    float s2 = fminf(nh, LC)/nh * Rinv;
    float tx = z.x*s2, ty = z.y*s2, tz = z.z*s2, tw = z.w*s2;
    float tot = blk_sum(tx*tx + ty*ty + tz*tz + tw*tw, sb);
    float n  = fmaxf(sqrtf(tot), EPSF);
    float s3 = fminf(n, LC)/n;
    float4 o4 = make_float4(rnd_t(tx*s3), rnd_t(ty*s3), rnd_t(tz*s3), rnd_t(tw*s3));
    *(float4*)(out + (size_t)row*D + h*HDIM + c) = o4;
}

// ---------------- clipnorm over FF=4096 row (tf32-rounded out) ----------------
__global__ __launch_bounds__(256) void k_rownorm_ff(float* __restrict__ X){
    __shared__ float sb[8];
    const float LC = atanhf(MAXT);
    size_t base = (size_t)blockIdx.x * FFD;
    int t = threadIdx.x;
    float v[16]; float ss = 0.f;
#pragma unroll
    for (int i=0;i<16;i++){ v[i] = X[base + t + i*256]; ss += v[i]*v[i]; }
    ss = blk_sum(ss, sb);
    float n = fmaxf(sqrtf(ss), EPSF);
    float s1 = fminf(n, LC)/n;
#pragma unroll
    for (int i=0;i<16;i++) X[base + t + i*256] = rnd_t(v[i]*s1);
}

// ---------------- gate*clip, expmap0, mobius_add with residual ----------------
template<bool PREP>
__global__ __launch_bounds__(256) void k_resmix(const float* __restrict__ Z, int g_off,
                                                const float* __restrict__ res,
                                                float* __restrict__ out,
                                                int sh_off, int sc_off,
                                                float* __restrict__ tm){
    __shared__ float sb[8];
    const float LC = atanhf(MAXT);
    int row = blockIdx.x, b = row >> 10;
    int t = threadIdx.x;
    size_t base = (size_t)row * D;
    float z[4], r0[4], gg[4];
#pragma unroll
    for (int i=0;i<4;i++){
        int d0 = t + i*256;
        z[i]  = Z[base + d0];
        r0[i] = res[base + d0];
        gg[i] = g_ada[b*6*D + g_off + d0];
    }
    float ss = 0.f;
#pragma unroll
    for (int i=0;i<4;i++) ss += z[i]*z[i];
    ss = blk_sum(ss, sb);
    float n  = fmaxf(sqrtf(ss), EPSF);
    float s1 = fminf(n, LC)/n;
    float tt[4]; float st = 0.f;
#pragma unroll
    for (int i=0;i<4;i++){ tt[i] = gg[i]*(z[i]*s1); st += tt[i]*tt[i]; }
    st = blk_sum(st, sb);
    float nt  = fmaxf(sqrtf(st), EPSF);
    float ysc = tanhf(nt)/nt;
    float y[4];
#pragma unroll
    for (int i=0;i<4;i++) y[i] = tt[i]*ysc;
    float x2=0.f, y2=0.f, xy=0.f;
#pragma unroll
    for (int i=0;i<4;i++){ x2 += r0[i]*r0[i]; y2 += y[i]*y[i]; xy += r0[i]*y[i]; }
    x2 = blk_sum(x2, sb);
    y2 = blk_sum(y2, sb);
    xy = blk_sum(xy, sb);
    float den = fmaxf(1.0f + 2.0f*xy + x2*y2, EPSF);
    float ca  = 1.0f + 2.0f*xy + y2;
    float cb  = 1.0f - x2;
    float o[4];
#pragma unroll
    for (int i=0;i<4;i++){
        o[i] = (ca*r0[i] + cb*y[i]) / den;
        out[base + t + i*256] = o[i];
    }
    if (PREP){
        float ss2 = 0.f;
#pragma unroll
        for (int i=0;i<4;i++) ss2 += o[i]*o[i];
        ss2 = blk_sum(ss2, sb);
        float n2 = fmaxf(sqrtf(ss2), EPSF);
        float a2 = fminf(fmaxf(n2, EPSF), MAXT);
        float ls = atanhf(a2) / n2;
        float u[4];
#pragma unroll
        for (int i=0;i<4;i++) u[i] = o[i]*ls;
        float m = blk_sum(u[0]+u[1]+u[2]+u[3], sb) * (1.0f/D);
        float vv = 0.f;
#pragma unroll
        for (int i=0;i<4;i++){ float dd = u[i]-m; vv += dd*dd; }
        vv = blk_sum(vv, sb) * (1.0f/D);
        float inv = rsqrtf(vv + 1e-6f);
        const float* ad = g_ada + b*6*D;
        float v[4]; float s2 = 0.f;
#pragma unroll
        for (int i=0;i<4;i++){
            int d0 = t + i*256;
            float xn  = (u[i]-m)*inv;
            float val = xn * (1.0f + ad[sc_off + d0]) + ad[sh_off + d0];
            v[i] = val; s2 += val*val;
        }
        s2 = blk_sum(s2, sb);
        float nv = fmaxf(sqrtf(s2), EPSF);
        float cl = fminf(nv, LC) / nv;
#pragma unroll
        for (int i=0;i<4;i++) tm[base + t + i*256] = rnd_t(v[i]*cl);
    }
}

// ---------------- fused flash attention (tf32 mma, online softmax) ----------------
#define QK_STRIDE 68
#define V_STRIDE  72
__global__ __launch_bounds__(256) void k_fattn(const float* __restrict__ qt,
                                               const float* __restrict__ kt,
                                               const float* __restrict__ vt,
                                               float* __restrict__ att){
    extern __shared__ unsigned smem_u[];
    unsigned* Qs = smem_u;
    unsigned* Ks = smem_u + 128*QK_STRIDE;
    unsigned* Vs = smem_u + 2*128*QK_STRIDE;

    const int tid = threadIdx.x, lane = tid & 31, wid = tid >> 5;
    const int gid = lane >> 2, tg = lane & 3;
    const int bh = blockIdx.y, q0 = blockIdx.x * 128;
    const float* Qb = qt + ((size_t)bh*SQ + q0)*HDIM;
    const float* Kb = kt + (size_t)bh*SQ*HDIM;
    const float* Vb = vt + (size_t)bh*SQ*HDIM;

#pragma unroll
    for (int it=0; it<8; it++){
        int row = it*16 + (tid>>4);
        int c4  = (tid & 15)*4;
        float4 v = *(const float4*)(Qb + (size_t)row*HDIM + c4);
        *(uint4*)&Qs[row*QK_STRIDE + c4] = cvt4(v);
    }

    float oacc[8][4];
#pragma unroll
    for (int i=0;i<8;i++){ oacc[i][0]=0.f; oacc[i][1]=0.f; oacc[i][2]=0.f; oacc[i][3]=0.f; }
    float m0 = -1e30f, m1 = -1e30f, l0 = 0.f, l1 = 0.f;
    const int qr = wid*16 + gid;

    for (int j=0; j<SQ/128; j++){
        __syncthreads();
#pragma unroll
        for (int it=0; it<8; it++){
            int row = it*16 + (tid>>4);
            int c4  = (tid & 15)*4;
            const float* kp = Kb + (size_t)(j*128+row)*HDIM + c4;
            *(uint4*)&Ks[row*QK_STRIDE + c4] = cvt4(*(const float4*)kp);
            const float* vp = Vb + (size_t)(j*128+row)*HDIM + c4;
            int r8 = row & 7;
            int s  = (r8 & 1) ? 4 + (r8>>1) : (r8>>1);
            int pr = (row & ~7) | s;
            *(uint4*)&Vs[pr*V_STRIDE + c4] = cvt4(*(const float4*)vp);
        }
        __syncthreads();

        float sf[16][4];
#pragma unroll
        for (int nt=0; nt<16; nt++){ sf[nt][0]=0.f; sf[nt][1]=0.f; sf[nt][2]=0.f; sf[nt][3]=0.f; }
#pragma unroll
        for (int ks=0; ks<8; ks++){
            unsigned a[4];
            a[0] = Qs[(qr  )*QK_STRIDE + ks*8 + tg  ];
            a[1] = Qs[(qr+8)*QK_STRIDE + ks*8 + tg  ];
            a[2] = Qs[(qr  )*QK_STRIDE + ks*8 + tg+4];
            a[3] = Qs[(qr+8)*QK_STRIDE + ks*8 + tg+4];
#pragma unroll
            for (int nt=0; nt<16; nt++){
                unsigned b[2];
                b[0] = Ks[(nt*8+gid)*QK_STRIDE + ks*8 + tg  ];
                b[1] = Ks[(nt*8+gid)*QK_STRIDE + ks*8 + tg+4];
                mma_tf32(sf[nt], a, b);
            }
        }
        float mx0 = -1e30f, mx1 = -1e30f;
#pragma unroll
        for (int nt=0; nt<16; nt++){
            sf[nt][0] *= 0.125f; sf[nt][1] *= 0.125f;
            sf[nt][2] *= 0.125f; sf[nt][3] *= 0.125f;
            mx0 = fmaxf(mx0, fmaxf(sf[nt][0], sf[nt][1]));
            mx1 = fmaxf(mx1, fmaxf(sf[nt][2], sf[nt][3]));
        }
        mx0 = fmaxf(mx0, __shfl_xor_sync(0xffffffffu, mx0, 1));
        mx0 = fmaxf(mx0, __shfl_xor_sync(0xffffffffu, mx0, 2));
        mx1 = fmaxf(mx1, __shfl_xor_sync(0xffffffffu, mx1, 1));
        mx1 = fmaxf(mx1, __shfl_xor_sync(0xffffffffu, mx1, 2));
        float m0n = fmaxf(m0, mx0), m1n = fmaxf(m1, mx1);
        float sc0 = __expf(m0 - m0n), sc1 = __expf(m1 - m1n);
        m0 = m0n; m1 = m1n;
        float rs0 = 0.f, rs1 = 0.f;
        unsigned paf[16][4];
#pragma unroll
        for (int nt=0; nt<16; nt++){
            float p0 = __expf(sf[nt][0] - m0n);
            float p1 = __expf(sf[nt][1] - m0n);
            float p2 = __expf(sf[nt][2] - m1n);
            float p3 = __expf(sf[nt][3] - m1n);
            rs0 += p0 + p1; rs1 += p2 + p3;
            paf[nt][0] = f2t(p0); paf[nt][1] = f2t(p2);
            paf[nt][2] = f2t(p1); paf[nt][3] = f2t(p3);
        }
        rs0 += __shfl_xor_sync(0xffffffffu, rs0, 1);
        rs0 += __shfl_xor_sync(0xffffffffu, rs0, 2);
        rs1 += __shfl_xor_sync(0xffffffffu, rs1, 1);
        rs1 += __shfl_xor_sync(0xffffffffu, rs1, 2);
        l0 = l0*sc0 + rs0; l1 = l1*sc1 + rs1;
#pragma unroll
        for (int d0=0; d0<8; d0++){
            oacc[d0][0] *= sc0; oacc[d0][1] *= sc0;
            oacc[d0][2] *= sc1; oacc[d0][3] *= sc1;
        }
#pragma unroll
        for (int ks=0; ks<16; ks++){
#pragma unroll
            for (int d0=0; d0<8; d0++){
                unsigned b[2];
                b[0] = Vs[(ks*8 + tg  )*V_STRIDE + d0*8 + gid];
                b[1] = Vs[(ks*8 + tg+4)*V_STRIDE + d0*8 + gid];
                mma_tf32(oacc[d0], paf[ks], b);
            }
        }
    }
    float il0 = 1.f / l0, il1 = 1.f / l1;
    float* Ob = att + ((size_t)bh*SQ + q0)*HDIM;
#pragma unroll
    for (int d0=0; d0<8; d0++){
        int c = d0*8 + 2*tg;
        *(float2*)(Ob + (size_t)qr*HDIM + c)     = make_float2(oacc[d0][0]*il0, oacc[d0][1]*il0);
        *(float2*)(Ob + (size_t)(qr+8)*HDIM + c) = make_float2(oacc[d0][2]*il1, oacc[d0][3]*il1);
    }
}

// ---------------- TF32 GEMM: cp.async pipeline + ldmatrix fragments ----------------
// A [M,K] row-major (tf32-pre-rounded), Bt [N,K] row-major (transposed weights).
// Block 128x128, BK=16, 256 threads (8 warps 2x4, warp 64x32).
// SMEM: both tiles 128 rows x 16 k, stride 20 floats (5r mod 8 permutation =>
// conflict-free ldmatrix phases). Inner loop: 6 LDSM.x4 + 16 HMMA per 8-k.
#define STAGES 4
#define A_ST (128*20)
#define B_ST (128*20)
__global__ __launch_bounds__(256) void k_mma(
    const float* __restrict__ A, const float* __restrict__ Bt, size_t strideB,
    const float* __restrict__ bz0, const float* __restrict__ bz1, const float* __restrict__ bz2,
    float* __restrict__ C, size_t strideC, int N, int K)
{
    extern __shared__ float sm_f[];
    float* As = sm_f;
    float* Bs = sm_f + STAGES*A_ST;
    const int tid = threadIdx.x, lane = tid & 31, wid = tid >> 5;
    const int wm = wid >> 2, wn = wid & 3;
    const int gid = lane >> 2, tg = lane & 3;
    const int z = blockIdx.z;
    const float* Bb = Bt + (size_t)z*strideB;
    const float* bias = (z==0) ? bz0 : ((z==1) ? bz1 : bz2);
    float* Cb = C + (size_t)z*strideC;
    const int m0 = blockIdx.y * 128;
    const int n0 = blockIdx.x * 128;
    const int KT = K >> 4;

    const unsigned sA = (unsigned)__cvta_generic_to_shared(As);
    const unsigned sB = (unsigned)__cvta_generic_to_shared(Bs);
    // ldmatrix per-lane row addresses (bytes):
    // A x4 (per im): rows mr + (lane&15), k-half (lane>>4)
    const unsigned aoff = ((wm*64 + (lane & 15))*20 + (lane >> 4)*4) * 4;
    // B x4 (per in-pair): n rows wn*32 + pairbase + (lane&7), k-half (lane>>3)&1
    const unsigned boff = ((wn*32 + ((lane >> 4) << 3) + (lane & 7))*20 + ((lane >> 3) & 1)*4) * 4;

    float acc[4][4][4];
#pragma unroll
    for (int i=0;i<4;i++)
#pragma unroll
        for (int j=0;j<4;j++)
#pragma unroll
            for (int r=0;r<4;r++) acc[i][j][r] = 0.f;

    auto issue = [&](int kt){
        int s = kt & (STAGES-1);
        float* as = As + s*A_ST;
        float* bs = Bs + s*B_ST;
        int kb = kt << 4;
#pragma unroll
        for (int it=0; it<2; it++){
            int idx = tid*2 + it;
            int row = idx >> 2, c4 = (idx & 3)*4;
            cp16(&as[row*20 + c4], A  + (size_t)(m0+row)*K + kb + c4);
        }
#pragma unroll
        for (int it=0; it<2; it++){
            int idx = tid*2 + it;
            int row = idx >> 2, c4 = (idx & 3)*4;
            cp16(&bs[row*20 + c4], Bb + (size_t)(n0+row)*K + kb + c4);
        }
        asm volatile("cp.async.commit_group;");
    };

    issue(0); issue(1); issue(2);   // KT >= 64 always

    for (int kt=0; kt<KT; kt++){
        asm volatile("cp.async.wait_group %0;" :: "n"(STAGES-2));
        __syncthreads();
        if (kt + STAGES-1 < KT) issue(kt + STAGES-1);
        int s = kt & (STAGES-1);
        unsigned abase = sA + s*(A_ST*4) + aoff;
        unsigned bbase = sB + s*(B_ST*4) + boff;
#pragma unroll
        for (int ks=0; ks<16; ks+=8){
            unsigned af[4][4], bf[4][2];
#pragma unroll
            for (int im=0; im<4; im++)
                ldsm4(abase + (im*16*20 + ks)*4,
                      af[im][0], af[im][1], af[im][2], af[im][3]);
            ldsm4(bbase + ks*4,            bf[0][0], bf[0][1], bf[1][0], bf[1][1]);
            ldsm4(bbase + (16*20 + ks)*4,  bf[2][0], bf[2][1], bf[3][0], bf[3][1]);
#pragma unroll
            for (int im=0; im<4; im++)
#pragma unroll
                for (int in=0; in<4; in++)
                    mma_tf32(acc[im][in], af[im], bf[in]);
        }
    }

    // epilogue: C layout c0=(r,2tg) c1=(r,2tg+1) c2=(r+8,2tg) c3=(r+8,2tg+1)
#pragma unroll
    for (int im=0; im<4; im++){
        int r0 = m0 + wm*64 + im*16 + gid;
#pragma unroll
        for (int in=0; in<4; in++){
            int c = n0 + wn*32 + in*8 + tg*2;
            float b0 = bias[c], b1 = bias[c+1];
            *(float2*)(Cb + (size_t)r0*N + c) =
                make_float2(acc[im][in][0] + b0, acc[im][in][1] + b1);
            *(float2*)(Cb + (size_t)(r0+8)*N + c) =
                make_float2(acc[im][in][2] + b0, acc[im][in][3] + b1);
        }
    }
}

// ---------------- host launch ----------------
extern "C" void kernel_launch(void* const* d_in, const int* in_sizes, int n_in,
                              void* d_out, int out_size){
    (void)in_sizes; (void)n_in; (void)out_size;
    const float* x     = (const float*)d_in[0];
    const float* temb  = (const float*)d_in[1];
    const float* w_q   = (const float*)d_in[2];
    const float* b_q   = (const float*)d_in[3];
    const float* w_k   = (const float*)d_in[4];
    const float* b_k   = (const float*)d_in[5];
    const float* w_v   = (const float*)d_in[6];
    const float* b_v   = (const float*)d_in[7];
    const float* w_o   = (const float*)d_in[8];
    const float* b_o   = (const float*)d_in[9];
    const float* w_f1  = (const float*)d_in[10];
    const float* b_f1  = (const float*)d_in[11];
    const float* w_f2  = (const float*)d_in[12];
    const float* b_f2  = (const float*)d_in[13];
    const float* w_ada = (const float*)d_in[14];
    const float* b_ada = (const float*)d_in[15];
    float* out = (float*)d_out;

    float *tm, *lin3, *qkvt, *att, *tcat, *zb, *xnew, *big, *wbuf;
    cudaGetSymbolAddress((void**)&tm,   g_tm);
    cudaGetSymbolAddress((void**)&lin3, g_lin3);
    cudaGetSymbolAddress((void**)&qkvt, g_qkvt);
    cudaGetSymbolAddress((void**)&att,  g_att);
    cudaGetSymbolAddress((void**)&tcat, g_tcat);
    cudaGetSymbolAddress((void**)&zb,   g_zb);
    cudaGetSymbolAddress((void**)&xnew, g_xnew);
    cudaGetSymbolAddress((void**)&big,  g_big);
    cudaGetSymbolAddress((void**)&wbuf, g_w);

    double lgn = lgamma(512.0) + lgamma(0.5) - lgamma(512.5);
    double lgh = lgamma(32.0)  + lgamma(0.5) - lgamma(32.5);
    double betaN = exp(lgn), betaH = exp(lgh);
    float R    = (float)(betaH / betaN);
    float Rinv = (float)(betaN / betaH);

    const int fa_smem  = (2*128*QK_STRIDE + 128*V_STRIDE) * 4;
    const int mma_smem = STAGES*(A_ST + B_ST)*4;
    cudaFuncSetAttribute(k_fattn, cudaFuncAttributeMaxDynamicSharedMemorySize, fa_smem);
    cudaFuncSetAttribute(k_mma,   cudaFuncAttributeMaxDynamicSharedMemorySize, mma_smem);

    const size_t ND = (size_t)NROWS*D;

    // round + transpose all weights into g_w: [q|k|v|o|f1|f2], each [N,K]
    k_transp<<<dim3(128,128,6),256>>>(w_q, w_k, w_v, w_o, w_f1, w_f2, wbuf);

    // ada
    k_ada<<<dim3(24,4,1), 256>>>(temb, w_ada, b_ada);

    // ---- attention block ----
    k_prep<<<NROWS, 256>>>(x, /*sh*/0, /*sc*/D, tm);

    // QKV fused over blockIdx.z
    k_mma<<<dim3(8,32,3),256,mma_smem>>>(tm, wbuf, WSZ, b_q, b_k, b_v,
                                         lin3, ND, 1024, 1024);
    k_heads<<<dim3(NROWS,3,1),256>>>(lin3, qkvt, R);

    k_fattn<<<dim3(SQ/128, BB*NH), 256, fa_smem>>>(qkvt, qkvt+ND, qkvt+2*ND, att);

    k_merge<<<NROWS,256>>>(att, tcat, Rinv);
    k_mma<<<dim3(8,32,1),256,mma_smem>>>(tcat, wbuf+3*WSZ, 0, b_o, b_o, b_o,
                                         zb, 0, 1024, 1024);
    k_resmix<true><<<NROWS,256>>>(zb, /*gate*/2*D, x, xnew, /*sh*/3*D, /*sc*/4*D, tm);

    // ---- FFN block ----
    k_mma<<<dim3(32,32,1),256,mma_smem>>>(tm, wbuf+4*WSZ, 0, b_f1, b_f1, b_f1,
                                          big, 0, 4096, 1024);
    k_rownorm_ff<<<NROWS,256>>>(big);
    k_mma<<<dim3(8,32,1),256,mma_smem>>>(big, wbuf+8*WSZ, 0, b_f2, b_f2, b_f2,
                                         zb, 0, 1024, 4096);
    k_resmix<false><<<NROWS,256>>>(zb, /*gate*/5*D, xnew, out, 0, 0, nullptr);
}

// round 16
// speedup vs baseline: 1.4508x; 1.4508x over previous
#include <cuda_runtime.h>
#include <math.h>

#define D     1024
#define SQ    1024          // sequence length
#define BB    4             // batch
#define NH    16            // heads
#define HDIM  64            // head dim
#define FFD   4096
#define NROWS 4096          // BB*SQ
#define EPSF  1e-7f
#define MAXT  0.99999f      // 1 - 1e-5 (as float)
#define WSZ   ((size_t)D*D) // 1M floats per D x D weight

// ---------------- scratch (static device memory; no runtime allocation) ----------------
__device__ __align__(16) float g_ada [BB*6*D];
__device__ __align__(16) float g_tm  [NROWS*D];
__device__ __align__(16) float g_lin3[(size_t)3*NROWS*D];
__device__ __align__(16) float g_qkvt[(size_t)3*NROWS*D];
__device__ __align__(16) float g_att [NROWS*D];
__device__ __align__(16) float g_tcat[NROWS*D];
__device__ __align__(16) float g_zb  [NROWS*D];
__device__ __align__(16) float g_xnew[NROWS*D];
__device__ __align__(16) float g_big [(size_t)NROWS*FFD];   // FFN hidden
__device__ __align__(16) float g_w   [(size_t)12*1024*1024]; // tf32-rounded weights [K,N]

// ---------------- reduction helpers (blockDim == 256) ----------------
__device__ __forceinline__ float warp_sum(float v){
#pragma unroll
    for (int o=16;o;o>>=1) v += __shfl_xor_sync(0xffffffffu, v, o);
    return v;
}
__device__ __forceinline__ float blk_sum(float v, float* sb){
    int lane = threadIdx.x & 31, w = threadIdx.x >> 5;
    v = warp_sum(v);
    __syncthreads();
    if (lane == 0) sb[w] = v;
    __syncthreads();
    float r = 0.f;
#pragma unroll
    for (int i=0;i<8;i++) r += sb[i];
    return r;
}

// ---------------- tf32 helpers ----------------
__device__ __forceinline__ unsigned f2t(float f){
    unsigned u; asm("cvt.rna.tf32.f32 %0, %1;" : "=r"(u) : "f"(f)); return u;
}
__device__ __forceinline__ float rnd_t(float f){ return __uint_as_float(f2t(f)); }
__device__ __forceinline__ uint4 cvt4(float4 v){
    return make_uint4(f2t(v.x), f2t(v.y), f2t(v.z), f2t(v.w));
}
__device__ __forceinline__ void mma_tf32(float* d, const unsigned* a, const unsigned* b){
    asm volatile("mma.sync.aligned.m16n8k8.row.col.f32.tf32.tf32.f32 "
        "{%0,%1,%2,%3}, {%4,%5,%6,%7}, {%8,%9}, {%0,%1,%2,%3};"
        : "+f"(d[0]), "+f"(d[1]), "+f"(d[2]), "+f"(d[3])
        : "r"(a[0]), "r"(a[1]), "r"(a[2]), "r"(a[3]), "r"(b[0]), "r"(b[1]));
}
__device__ __forceinline__ void cp16(void* sp, const void* gp){
    unsigned sa = (unsigned)__cvta_generic_to_shared(sp);
    asm volatile("cp.async.cg.shared.global [%0], [%1], 16;" :: "r"(sa), "l"(gp));
}
// ldmatrix x4 on tf32 data (each 32-bit element = one b16 pair)
__device__ __forceinline__ void ldsm4(unsigned addr, unsigned &r0, unsigned &r1,
                                      unsigned &r2, unsigned &r3){
    asm volatile("ldmatrix.sync.aligned.m8n8.x4.shared.b16 {%0,%1,%2,%3}, [%4];"
        : "=r"(r0), "=r"(r1), "=r"(r2), "=r"(r3) : "r"(addr));
}

// ---------------- round weights to tf32 (RN) once per call ----------------
__global__ __launch_bounds__(256) void k_round6(
    const float* __restrict__ s0, const float* __restrict__ s1,
    const float* __restrict__ s2, const float* __restrict__ s3,
    const float* __restrict__ s4, const float* __restrict__ s5,
    float* __restrict__ dst)
{
    const float* srcs[6] = {s0,s1,s2,s3,s4,s5};
    const int offs [6] = {0, 1<<20, 2<<20, 3<<20, 4<<20, 8<<20};
    const int sizes[6] = {1<<20, 1<<20, 1<<20, 1<<20, 1<<22, 1<<22};
    int y = blockIdx.y;
    int i4 = (blockIdx.x*256 + threadIdx.x)*4;
    if (i4 < sizes[y]){
        float4 v = *(const float4*)(srcs[y] + i4);
        uint4 u = cvt4(v);
        *(float4*)(dst + offs[y] + i4) = *(float4*)&u;
    }
}

// ---------------- ada = t_emb @ w_ada + b_ada ----------------
__global__ __launch_bounds__(256) void k_ada(const float* __restrict__ temb,
                                             const float* __restrict__ w,
                                             const float* __restrict__ bias){
    __shared__ float ts[D];
    int b = blockIdx.y;
    int j = blockIdx.x * 256 + threadIdx.x;
    for (int i = threadIdx.x; i < D; i += 256) ts[i] = temb[b*D + i];
    __syncthreads();
    float acc = bias[j];
    const float* wp = w + j;
#pragma unroll 4
    for (int k = 0; k < D; k++) acc += ts[k] * wp[(size_t)k * (6*D)];
    g_ada[b*6*D + j] = acc;
}

// ---------------- logmap0 + layernorm + modulation + clipnorm (tf32-rounded out) ----------------
__global__ __launch_bounds__(256) void k_prep(const float* __restrict__ P,
                                              int sh_off, int sc_off,
                                              float* __restrict__ out){
    __shared__ float sb[8];
    const float LC = atanhf(MAXT);
    int row = blockIdx.x, b = row >> 10;
    int t = threadIdx.x;
    const float* xr = P + (size_t)row * D;
    float x0[4];
#pragma unroll
    for (int i=0;i<4;i++) x0[i] = xr[t + i*256];
    float ss = 0.f;
#pragma unroll
    for (int i=0;i<4;i++) ss += x0[i]*x0[i];
    ss = blk_sum(ss, sb);
    float n  = fmaxf(sqrtf(ss), EPSF);
    float a  = fminf(fmaxf(n, EPSF), MAXT);
    float ls = atanhf(a) / n;
    float u[4];
#pragma unroll
    for (int i=0;i<4;i++) u[i] = x0[i]*ls;
    float m = blk_sum(u[0]+u[1]+u[2]+u[3], sb) * (1.0f/D);
    float vv = 0.f;
#pragma unroll
    for (int i=0;i<4;i++){ float d0 = u[i]-m; vv += d0*d0; }
    vv = blk_sum(vv, sb) * (1.0f/D);
    float inv = rsqrtf(vv + 1e-6f);
    const float* ad = g_ada + b*6*D;
    float v[4]; float s2 = 0.f;
#pragma unroll
    for (int i=0;i<4;i++){
        int d0 = t + i*256;
        float xn  = (u[i]-m)*inv;
        float val = xn * (1.0f + ad[sc_off + d0]) + ad[sh_off + d0];
        v[i] = val; s2 += val*val;
    }
    s2 = blk_sum(s2, sb);
    float nv = fmaxf(sqrtf(s2), EPSF);
    float cl = fminf(nv, LC) / nv;
#pragma unroll
    for (int i=0;i<4;i++) out[(size_t)row*D + t + i*256] = rnd_t(v[i]*cl);
}

// ---------------- beta-split to heads (q/k/v via blockIdx.y) ----------------
__global__ __launch_bounds__(256) void k_heads(const float* __restrict__ lin3,
                                               float* __restrict__ qkvt, float Rf){
    __shared__ float sb[8];
    const float LC = atanhf(MAXT);
    int row = blockIdx.x, b = row >> 10, s = row & 1023;
    const float* lin = lin3 + (size_t)blockIdx.y*NROWS*D;
    float* out = qkvt + (size_t)blockIdx.y*NROWS*D;
    int t = threadIdx.x, h = t >> 4, c = (t & 15) * 4;
    float4 z = *(const float4*)(lin + (size_t)row*D + h*HDIM + c);
    float ss = z.x*z.x + z.y*z.y + z.z*z.z + z.w*z.w;
    float tot = blk_sum(ss, sb);
    float n  = fmaxf(sqrtf(tot), EPSF);
    float s1 = fminf(n, LC)/n * Rf;
    float tx = z.x*s1, ty = z.y*s1, tz = z.z*s1, tw = z.w*s1;
    float hs = tx*tx + ty*ty + tz*tz + tw*tw;
#pragma unroll
    for (int o=1;o<16;o<<=1) hs += __shfl_xor_sync(0xffffffffu, hs, o);
    float nh = fmaxf(sqrtf(hs), EPSF);
    float s2 = fminf(nh, LC)/nh;
    float4 o4 = make_float4(rnd_t(tx*s2), rnd_t(ty*s2), rnd_t(tz*s2), rnd_t(tw*s2));
    *(float4*)(out + ((size_t)(b*NH + h)*SQ + s)*HDIM + c) = o4;
}

// ---------------- merge heads (tf32-rounded out) ----------------
__global__ __launch_bounds__(256) void k_merge(const float* __restrict__ att,
                                               float* __restrict__ out, float Rinv){
    __shared__ float sb[8];
    const float LC = atanhf(MAXT);
    int row = blockIdx.x, b = row >> 10, s = row & 1023;
    int t = threadIdx.x, h = t >> 4, c = (t & 15) * 4;
    float4 z = *(const float4*)(att + ((size_t)(b*NH + h)*SQ + s)*HDIM + c);
    float hs = z.x*z.x + z.y*z.y + z.z*z.z + z.w*z.w;
#pragma unroll
    for (int o=1;o<16;o<<=1) hs += __shfl_xor_sync(0xffffffffu, hs, o);
    float nh = fmaxf(sqrtf(hs), EPSF);
    float s2 = fminf(nh, LC)/nh * Rinv;
    float tx = z.x*s2, ty = z.y*s2, tz = z.z*s2, tw = z.w*s2;
    float tot = blk_sum(tx*tx + ty*ty + tz*tz + tw*tw, sb);
    float n  = fmaxf(sqrtf(tot), EPSF);
    float s3 = fminf(n, LC)/n;
    float4 o4 = make_float4(rnd_t(tx*s3), rnd_t(ty*s3), rnd_t(tz*s3), rnd_t(tw*s3));
    *(float4*)(out + (size_t)row*D + h*HDIM + c) = o4;
}

// ---------------- clipnorm over FF=4096 row (tf32-rounded out) ----------------
__global__ __launch_bounds__(256) void k_rownorm_ff(float* __restrict__ X){
    __shared__ float sb[8];
    const float LC = atanhf(MAXT);
    size_t base = (size_t)blockIdx.x * FFD;
    int t = threadIdx.x;
    float v[16]; float ss = 0.f;
#pragma unroll
    for (int i=0;i<16;i++){ v[i] = X[base + t + i*256]; ss += v[i]*v[i]; }
    ss = blk_sum(ss, sb);
    float n = fmaxf(sqrtf(ss), EPSF);
    float s1 = fminf(n, LC)/n;
#pragma unroll
    for (int i=0;i<16;i++) X[base + t + i*256] = rnd_t(v[i]*s1);
}

// ---------------- gate*clip, expmap0, mobius_add with residual ----------------
template<bool PREP>
__global__ __launch_bounds__(256) void k_resmix(const float* __restrict__ Z, int g_off,
                                                const float* __restrict__ res,
                                                float* __restrict__ out,
                                                int sh_off, int sc_off,
                                                float* __restrict__ tm){
    __shared__ float sb[8];
    const float LC = atanhf(MAXT);
    int row = blockIdx.x, b = row >> 10;
    int t = threadIdx.x;
    size_t base = (size_t)row * D;
    float z[4], r0[4], gg[4];
#pragma unroll
    for (int i=0;i<4;i++){
        int d0 = t + i*256;
        z[i]  = Z[base + d0];
        r0[i] = res[base + d0];
        gg[i] = g_ada[b*6*D + g_off + d0];
    }
    float ss = 0.f;
#pragma unroll
    for (int i=0;i<4;i++) ss += z[i]*z[i];
    ss = blk_sum(ss, sb);
    float n  = fmaxf(sqrtf(ss), EPSF);
    float s1 = fminf(n, LC)/n;
    float tt[4]; float st = 0.f;
#pragma unroll
    for (int i=0;i<4;i++){ tt[i] = gg[i]*(z[i]*s1); st += tt[i]*tt[i]; }
    st = blk_sum(st, sb);
    float nt  = fmaxf(sqrtf(st), EPSF);
    float ysc = tanhf(nt)/nt;
    float y[4];
#pragma unroll
    for (int i=0;i<4;i++) y[i] = tt[i]*ysc;
    float x2=0.f, y2=0.f, xy=0.f;
#pragma unroll
    for (int i=0;i<4;i++){ x2 += r0[i]*r0[i]; y2 += y[i]*y[i]; xy += r0[i]*y[i]; }
    x2 = blk_sum(x2, sb);
    y2 = blk_sum(y2, sb);
    xy = blk_sum(xy, sb);
    float den = fmaxf(1.0f + 2.0f*xy + x2*y2, EPSF);
    float ca  = 1.0f + 2.0f*xy + y2;
    float cb  = 1.0f - x2;
    float o[4];
#pragma unroll
    for (int i=0;i<4;i++){
        o[i] = (ca*r0[i] + cb*y[i]) / den;
        out[base + t + i*256] = o[i];
    }
    if (PREP){
        float ss2 = 0.f;
#pragma unroll
        for (int i=0;i<4;i++) ss2 += o[i]*o[i];
        ss2 = blk_sum(ss2, sb);
        float n2 = fmaxf(sqrtf(ss2), EPSF);
        float a2 = fminf(fmaxf(n2, EPSF), MAXT);
        float ls = atanhf(a2) / n2;
        float u[4];
#pragma unroll
        for (int i=0;i<4;i++) u[i] = o[i]*ls;
        float m = blk_sum(u[0]+u[1]+u[2]+u[3], sb) * (1.0f/D);
        float vv = 0.f;
#pragma unroll
        for (int i=0;i<4;i++){ float dd = u[i]-m; vv += dd*dd; }
        vv = blk_sum(vv, sb) * (1.0f/D);
        float inv = rsqrtf(vv + 1e-6f);
        const float* ad = g_ada + b*6*D;
        float v[4]; float s2 = 0.f;
#pragma unroll
        for (int i=0;i<4;i++){
            int d0 = t + i*256;
            float xn  = (u[i]-m)*inv;
            float val = xn * (1.0f + ad[sc_off + d0]) + ad[sh_off + d0];
            v[i] = val; s2 += val*val;
        }
        s2 = blk_sum(s2, sb);
        float nv = fmaxf(sqrtf(s2), EPSF);
        float cl = fminf(nv, LC) / nv;
#pragma unroll
        for (int i=0;i<4;i++) tm[base + t + i*256] = rnd_t(v[i]*cl);
    }
}

// ---------------- fused flash attention (tf32 mma, online softmax) ----------------
#define QK_STRIDE 68
#define V_STRIDE  72
__global__ __launch_bounds__(256) void k_fattn(const float* __restrict__ qt,
                                               const float* __restrict__ kt,
                                               const float* __restrict__ vt,
                                               float* __restrict__ att){
    extern __shared__ unsigned smem_u[];
    unsigned* Qs = smem_u;
    unsigned* Ks = smem_u + 128*QK_STRIDE;
    unsigned* Vs = smem_u + 2*128*QK_STRIDE;

    const int tid = threadIdx.x, lane = tid & 31, wid = tid >> 5;
    const int gid = lane >> 2, tg = lane & 3;
    const int bh = blockIdx.y, q0 = blockIdx.x * 128;
    const float* Qb = qt + ((size_t)bh*SQ + q0)*HDIM;
    const float* Kb = kt + (size_t)bh*SQ*HDIM;
    const float* Vb = vt + (size_t)bh*SQ*HDIM;

#pragma unroll
    for (int it=0; it<8; it++){
        int row = it*16 + (tid>>4);
        int c4  = (tid & 15)*4;
        float4 v = *(const float4*)(Qb + (size_t)row*HDIM + c4);
        *(uint4*)&Qs[row*QK_STRIDE + c4] = cvt4(v);
    }

    float oacc[8][4];
#pragma unroll
    for (int i=0;i<8;i++){ oacc[i][0]=0.f; oacc[i][1]=0.f; oacc[i][2]=0.f; oacc[i][3]=0.f; }
    float m0 = -1e30f, m1 = -1e30f, l0 = 0.f, l1 = 0.f;
    const int qr = wid*16 + gid;

    for (int j=0; j<SQ/128; j++){
        __syncthreads();
#pragma unroll
        for (int it=0; it<8; it++){
            int row = it*16 + (tid>>4);
            int c4  = (tid & 15)*4;
            const float* kp = Kb + (size_t)(j*128+row)*HDIM + c4;
            *(uint4*)&Ks[row*QK_STRIDE + c4] = cvt4(*(const float4*)kp);
            const float* vp = Vb + (size_t)(j*128+row)*HDIM + c4;
            int r8 = row & 7;
            int s  = (r8 & 1) ? 4 + (r8>>1) : (r8>>1);
            int pr = (row & ~7) | s;
            *(uint4*)&Vs[pr*V_STRIDE + c4] = cvt4(*(const float4*)vp);
        }
        __syncthreads();

        float sf[16][4];
#pragma unroll
        for (int nt=0; nt<16; nt++){ sf[nt][0]=0.f; sf[nt][1]=0.f; sf[nt][2]=0.f; sf[nt][3]=0.f; }
#pragma unroll
        for (int ks=0; ks<8; ks++){
            unsigned a[4];
            a[0] = Qs[(qr  )*QK_STRIDE + ks*8 + tg  ];
            a[1] = Qs[(qr+8)*QK_STRIDE + ks*8 + tg  ];
            a[2] = Qs[(qr  )*QK_STRIDE + ks*8 + tg+4];
            a[3] = Qs[(qr+8)*QK_STRIDE + ks*8 + tg+4];
#pragma unroll
            for (int nt=0; nt<16; nt++){
                unsigned b[2];
                b[0] = Ks[(nt*8+gid)*QK_STRIDE + ks*8 + tg  ];
                b[1] = Ks[(nt*8+gid)*QK_STRIDE + ks*8 + tg+4];
                mma_tf32(sf[nt], a, b);
            }
        }
        float mx0 = -1e30f, mx1 = -1e30f;
#pragma unroll
        for (int nt=0; nt<16; nt++){
            sf[nt][0] *= 0.125f; sf[nt][1] *= 0.125f;
            sf[nt][2] *= 0.125f; sf[nt][3] *= 0.125f;
            mx0 = fmaxf(mx0, fmaxf(sf[nt][0], sf[nt][1]));
            mx1 = fmaxf(mx1, fmaxf(sf[nt][2], sf[nt][3]));
        }
        mx0 = fmaxf(mx0, __shfl_xor_sync(0xffffffffu, mx0, 1));
        mx0 = fmaxf(mx0, __shfl_xor_sync(0xffffffffu, mx0, 2));
        mx1 = fmaxf(mx1, __shfl_xor_sync(0xffffffffu, mx1, 1));
        mx1 = fmaxf(mx1, __shfl_xor_sync(0xffffffffu, mx1, 2));
        float m0n = fmaxf(m0, mx0), m1n = fmaxf(m1, mx1);
        float sc0 = __expf(m0 - m0n), sc1 = __expf(m1 - m1n);
        m0 = m0n; m1 = m1n;
        float rs0 = 0.f, rs1 = 0.f;
        unsigned paf[16][4];
#pragma unroll
        for (int nt=0; nt<16; nt++){
            float p0 = __expf(sf[nt][0] - m0n);
            float p1 = __expf(sf[nt][1] - m0n);
            float p2 = __expf(sf[nt][2] - m1n);
            float p3 = __expf(sf[nt][3] - m1n);
            rs0 += p0 + p1; rs1 += p2 + p3;
            paf[nt][0] = f2t(p0); paf[nt][1] = f2t(p2);
            paf[nt][2] = f2t(p1); paf[nt][3] = f2t(p3);
        }
        rs0 += __shfl_xor_sync(0xffffffffu, rs0, 1);
        rs0 += __shfl_xor_sync(0xffffffffu, rs0, 2);
        rs1 += __shfl_xor_sync(0xffffffffu, rs1, 1);
        rs1 += __shfl_xor_sync(0xffffffffu, rs1, 2);
        l0 = l0*sc0 + rs0; l1 = l1*sc1 + rs1;
#pragma unroll
        for (int d0=0; d0<8; d0++){
            oacc[d0][0] *= sc0; oacc[d0][1] *= sc0;
            oacc[d0][2] *= sc1; oacc[d0][3] *= sc1;
        }
#pragma unroll
        for (int ks=0; ks<16; ks++){
#pragma unroll
            for (int d0=0; d0<8; d0++){
                unsigned b[2];
                b[0] = Vs[(ks*8 + tg  )*V_STRIDE + d0*8 + gid];
                b[1] = Vs[(ks*8 + tg+4)*V_STRIDE + d0*8 + gid];
                mma_tf32(oacc[d0], paf[ks], b);
            }
        }
    }
    float il0 = 1.f / l0, il1 = 1.f / l1;
    float* Ob = att + ((size_t)bh*SQ + q0)*HDIM;
#pragma unroll
    for (int d0=0; d0<8; d0++){
        int c = d0*8 + 2*tg;
        *(float2*)(Ob + (size_t)qr*HDIM + c)     = make_float2(oacc[d0][0]*il0, oacc[d0][1]*il0);
        *(float2*)(Ob + (size_t)(qr+8)*HDIM + c) = make_float2(oacc[d0][2]*il1, oacc[d0][3]*il1);
    }
}

// ---------------- TF32 GEMM: BK=32, 3-stage cp.async, ldmatrix A-frags ----------------
// A [M,K] row-major, B [K,N] row-major (both tf32-pre-rounded; mma truncation exact).
// Block 128x128, BK=32, 256 threads (8 warps 2x4, warp 64x32), 2 blocks/SM.
// A smem stride 36 (banks 4r: ldmatrix phases conflict-free), B stride 136.
#define STAGES 3
#define A_ST (128*36)
#define B_ST (32*136)
__global__ __launch_bounds__(256, 2) void k_mma(
    const float* __restrict__ A, const float* __restrict__ Bw, size_t strideB,
    const float* __restrict__ bz0, const float* __restrict__ bz1, const float* __restrict__ bz2,
    float* __restrict__ C, size_t strideC, int N, int K)
{
    extern __shared__ float sm_f[];
    float* As = sm_f;
    float* Bs = sm_f + STAGES*A_ST;
    const int tid = threadIdx.x, lane = tid & 31, wid = tid >> 5;
    const int wm = wid >> 2, wn = wid & 3;
    const int gid = lane >> 2, tg = lane & 3;
    const int z = blockIdx.z;
    const float* Bb = Bw + (size_t)z*strideB;
    const float* bias = (z==0) ? bz0 : ((z==1) ? bz1 : bz2);
    float* Cb = C + (size_t)z*strideC;
    const int m0 = blockIdx.y * 128;
    const int n0 = blockIdx.x * 128;
    const int KT = K >> 5;

    const unsigned sA = (unsigned)__cvta_generic_to_shared(As);
    // ldmatrix x4 lane address: rows wm*64 + (lane&15), k-half (lane>>4)*4 floats
    const unsigned aoff = ((wm*64 + (lane & 15))*36 + (lane >> 4)*4) * 4;

    float acc[4][4][4];
#pragma unroll
    for (int i=0;i<4;i++)
#pragma unroll
        for (int j=0;j<4;j++)
#pragma unroll
            for (int r=0;r<4;r++) acc[i][j][r] = 0.f;

    auto issue = [&](int s, int kt){
        float* as = As + s*A_ST;
        float* bs = Bs + s*B_ST;
        int kb = kt << 5;
        // A tile: 128 rows x 32 floats (1024 16B chunks)
#pragma unroll
        for (int it=0; it<4; it++){
            int idx = it*256 + tid;
            int row = idx >> 3, c4 = (idx & 7)*4;
            cp16(&as[row*36 + c4], A + (size_t)(m0+row)*K + kb + c4);
        }
        // B tile: 32 rows x 128 floats
#pragma unroll
        for (int it=0; it<4; it++){
            int idx = it*256 + tid;
            int row = idx >> 5, c4 = (idx & 31)*4;
            cp16(&bs[row*136 + c4], Bb + (size_t)(kb+row)*N + n0 + c4);
        }
        asm volatile("cp.async.commit_group;");
    };

    auto comp = [&](int s){
        unsigned abase = sA + s*(A_ST*4) + aoff;
        const float* bs = Bs + s*B_ST;
#pragma unroll
        for (int ks=0; ks<32; ks+=8){
            unsigned af[4][4], bf[4][2];
#pragma unroll
            for (int im=0; im<4; im++)
                ldsm4(abase + (im*16*36 + ks)*4,
                      af[im][0], af[im][1], af[im][2], af[im][3]);
#pragma unroll
            for (int in=0; in<4; in++){
                int nc = wn*32 + in*8 + gid;
                bf[in][0] = __float_as_uint(bs[(ks+tg  )*136 + nc]);
                bf[in][1] = __float_as_uint(bs[(ks+tg+4)*136 + nc]);
            }
#pragma unroll
            for (int im=0; im<4; im++)
#pragma unroll
                for (int in=0; in<4; in++)
                    mma_tf32(acc[im][in], af[im], bf[in]);
        }
    };

    issue(0, 0);
    issue(1, 1);
    int sc = 0, si = 2;
    for (int kt=0; kt<KT; kt++){
        if (kt + 2 < KT){
            asm volatile("cp.async.wait_group 1;");
            __syncthreads();
            issue(si, kt+2);
            si = (si==2) ? 0 : si+1;
        } else {
            asm volatile("cp.async.wait_group 0;");   // exact drain on tail
            __syncthreads();
        }
        comp(sc);
        sc = (sc==2) ? 0 : sc+1;
        __syncthreads();   // stage sc fully consumed before another issue overwrites
    }

    // epilogue: C layout c0=(r,2tg) c1=(r,2tg+1) c2=(r+8,2tg) c3=(r+8,2tg+1)
#pragma unroll
    for (int im=0; im<4; im++){
        int r0 = m0 + wm*64 + im*16 + gid;
#pragma unroll
        for (int in=0; in<4; in++){
            int c = n0 + wn*32 + in*8 + tg*2;
            float b0 = bias[c], b1 = bias[c+1];
            *(float2*)(Cb + (size_t)r0*N + c) =
                make_float2(acc[im][in][0] + b0, acc[im][in][1] + b1);
            *(float2*)(Cb + (size_t)(r0+8)*N + c) =
                make_float2(acc[im][in][2] + b0, acc[im][in][3] + b1);
        }
    }
}

// ---------------- host launch ----------------
extern "C" void kernel_launch(void* const* d_in, const int* in_sizes, int n_in,
                              void* d_out, int out_size){
    (void)in_sizes; (void)n_in; (void)out_size;
    const float* x     = (const float*)d_in[0];
    const float* temb  = (const float*)d_in[1];
    const float* w_q   = (const float*)d_in[2];
    const float* b_q   = (const float*)d_in[3];
    const float* w_k   = (const float*)d_in[4];
    const float* b_k   = (const float*)d_in[5];
    const float* w_v   = (const float*)d_in[6];
    const float* b_v   = (const float*)d_in[7];
    const float* w_o   = (const float*)d_in[8];
    const float* b_o   = (const float*)d_in[9];
    const float* w_f1  = (const float*)d_in[10];
    const float* b_f1  = (const float*)d_in[11];
    const float* w_f2  = (const float*)d_in[12];
    const float* b_f2  = (const float*)d_in[13];
    const float* w_ada = (const float*)d_in[14];
    const float* b_ada = (const float*)d_in[15];
    float* out = (float*)d_out;

    float *tm, *lin3, *qkvt, *att, *tcat, *zb, *xnew, *big, *wbuf;
    cudaGetSymbolAddress((void**)&tm,   g_tm);
    cudaGetSymbolAddress((void**)&lin3, g_lin3);
    cudaGetSymbolAddress((void**)&qkvt, g_qkvt);
    cudaGetSymbolAddress((void**)&att,  g_att);
    cudaGetSymbolAddress((void**)&tcat, g_tcat);
    cudaGetSymbolAddress((void**)&zb,   g_zb);
    cudaGetSymbolAddress((void**)&xnew, g_xnew);
    cudaGetSymbolAddress((void**)&big,  g_big);
    cudaGetSymbolAddress((void**)&wbuf, g_w);

    double lgn = lgamma(512.0) + lgamma(0.5) - lgamma(512.5);
    double lgh = lgamma(32.0)  + lgamma(0.5) - lgamma(32.5);
    double betaN = exp(lgn), betaH = exp(lgh);
    float R    = (float)(betaH / betaN);
    float Rinv = (float)(betaN / betaH);

    const int fa_smem  = (2*128*QK_STRIDE + 128*V_STRIDE) * 4;
    const int mma_smem = STAGES*(A_ST + B_ST)*4;
    cudaFuncSetAttribute(k_fattn, cudaFuncAttributeMaxDynamicSharedMemorySize, fa_smem);
    cudaFuncSetAttribute(k_mma,   cudaFuncAttributeMaxDynamicSharedMemorySize, mma_smem);

    const size_t ND = (size_t)NROWS*D;

    // round all weights to tf32 (RN) into g_w: [q|k|v|o|f1|f2], layout [K,N]
    k_round6<<<dim3(4096,6,1),256>>>(w_q, w_k, w_v, w_o, w_f1, w_f2, wbuf);

    // ada
    k_ada<<<dim3(24,4,1), 256>>>(temb, w_ada, b_ada);

    // ---- attention block ----
    k_prep<<<NROWS, 256>>>(x, /*sh*/0, /*sc*/D, tm);

    // QKV fused over blockIdx.z
    k_mma<<<dim3(8,32,3),256,mma_smem>>>(tm, wbuf, WSZ, b_q, b_k, b_v,
                                         lin3, ND, 1024, 1024);
    k_heads<<<dim3(NROWS,3,1),256>>>(lin3, qkvt, R);

    k_fattn<<<dim3(SQ/128, BB*NH), 256, fa_smem>>>(qkvt, qkvt+ND, qkvt+2*ND, att);

    k_merge<<<NROWS,256>>>(att, tcat, Rinv);
    k_mma<<<dim3(8,32,1),256,mma_smem>>>(tcat, wbuf+3*WSZ, 0, b_o, b_o, b_o,
                                         zb, 0, 1024, 1024);
    k_resmix<true><<<NROWS,256>>>(zb, /*gate*/2*D, x, xnew, /*sh*/3*D, /*sc*/4*D, tm);

    // ---- FFN block ----
    k_mma<<<dim3(32,32,1),256,mma_smem>>>(tm, wbuf+4*WSZ, 0, b_f1, b_f1, b_f1,
                                          big, 0, 4096, 1024);
    k_rownorm_ff<<<NROWS,256>>>(big);
    k_mma<<<dim3(8,32,1),256,mma_smem>>>(big, wbuf+8*WSZ, 0, b_f2, b_f2, b_f2,
                                         zb, 0, 1024, 4096);
    k_resmix<false><<<NROWS,256>>>(zb, /*gate*/5*D, xnew, out, 0, 0, nullptr);
}

// round 17
// speedup vs baseline: 1.4540x; 1.0022x over previous
#include <cuda_runtime.h>
#include <math.h>

#define D     1024
#define SQ    1024          // sequence length
#define BB    4             // batch
#define NH    16            // heads
#define HDIM  64            // head dim
#define FFD   4096
#define NROWS 4096          // BB*SQ
#define EPSF  1e-7f
#define MAXT  0.99999f      // 1 - 1e-5 (as float)
#define WSZ   ((size_t)D*D) // 1M floats per D x D weight

// ---------------- scratch (static device memory; no runtime allocation) ----------------
__device__ __align__(16) float g_ada [BB*6*D];
__device__ __align__(16) float g_tm  [NROWS*D];
__device__ __align__(16) float g_lin3[(size_t)3*NROWS*D];
__device__ __align__(16) float g_qkvt[(size_t)3*NROWS*D];
__device__ __align__(16) float g_att [NROWS*D];
__device__ __align__(16) float g_tcat[NROWS*D];
__device__ __align__(16) float g_zb  [NROWS*D];
__device__ __align__(16) float g_xnew[NROWS*D];
__device__ __align__(16) float g_big [(size_t)NROWS*FFD];   // FFN hidden
__device__ __align__(16) float g_w   [(size_t)12*1024*1024]; // tf32-rounded weights [K,N]

// ---------------- reduction helpers (blockDim == 256) ----------------
__device__ __forceinline__ float warp_sum(float v){
#pragma unroll
    for (int o=16;o;o>>=1) v += __shfl_xor_sync(0xffffffffu, v, o);
    return v;
}
__device__ __forceinline__ float blk_sum(float v, float* sb){
    int lane = threadIdx.x & 31, w = threadIdx.x >> 5;
    v = warp_sum(v);
    __syncthreads();
    if (lane == 0) sb[w] = v;
    __syncthreads();
    float r = 0.f;
#pragma unroll
    for (int i=0;i<8;i++) r += sb[i];
    return r;
}

// ---------------- tf32 helpers ----------------
__device__ __forceinline__ unsigned f2t(float f){
    unsigned u; asm("cvt.rna.tf32.f32 %0, %1;" : "=r"(u) : "f"(f)); return u;
}
__device__ __forceinline__ float rnd_t(float f){ return __uint_as_float(f2t(f)); }
__device__ __forceinline__ uint4 cvt4(float4 v){
    return make_uint4(f2t(v.x), f2t(v.y), f2t(v.z), f2t(v.w));
}
__device__ __forceinline__ void mma_tf32(float* d, const unsigned* a, const unsigned* b){
    asm volatile("mma.sync.aligned.m16n8k8.row.col.f32.tf32.tf32.f32 "
        "{%0,%1,%2,%3}, {%4,%5,%6,%7}, {%8,%9}, {%0,%1,%2,%3};"
        : "+f"(d[0]), "+f"(d[1]), "+f"(d[2]), "+f"(d[3])
        : "r"(a[0]), "r"(a[1]), "r"(a[2]), "r"(a[3]), "r"(b[0]), "r"(b[1]));
}
__device__ __forceinline__ void cp16(void* sp, const void* gp){
    unsigned sa = (unsigned)__cvta_generic_to_shared(sp);
    asm volatile("cp.async.cg.shared.global [%0], [%1], 16;" :: "r"(sa), "l"(gp));
}
// ldmatrix x4 on tf32 data (each 32-bit element = one b16 pair)
__device__ __forceinline__ void ldsm4(unsigned addr, unsigned &r0, unsigned &r1,
                                      unsigned &r2, unsigned &r3){
    asm volatile("ldmatrix.sync.aligned.m8n8.x4.shared.b16 {%0,%1,%2,%3}, [%4];"
        : "=r"(r0), "=r"(r1), "=r"(r2), "=r"(r3) : "r"(addr));
}

// ---------------- round weights to tf32 (RN) once per call ----------------
__global__ __launch_bounds__(256) void k_round6(
    const float* __restrict__ s0, const float* __restrict__ s1,
    const float* __restrict__ s2, const float* __restrict__ s3,
    const float* __restrict__ s4, const float* __restrict__ s5,
    float* __restrict__ dst)
{
    const float* srcs[6] = {s0,s1,s2,s3,s4,s5};
    const int offs [6] = {0, 1<<20, 2<<20, 3<<20, 4<<20, 8<<20};
    const int sizes[6] = {1<<20, 1<<20, 1<<20, 1<<20, 1<<22, 1<<22};
    int y = blockIdx.y;
    int i4 = (blockIdx.x*256 + threadIdx.x)*4;
    if (i4 < sizes[y]){
        float4 v = *(const float4*)(srcs[y] + i4);
        uint4 u = cvt4(v);
        *(float4*)(dst + offs[y] + i4) = *(float4*)&u;
    }
}

// ---------------- ada = t_emb @ w_ada + b_ada ----------------
__global__ __launch_bounds__(256) void k_ada(const float* __restrict__ temb,
                                             const float* __restrict__ w,
                                             const float* __restrict__ bias){
    __shared__ float ts[D];
    int b = blockIdx.y;
    int j = blockIdx.x * 256 + threadIdx.x;
    for (int i = threadIdx.x; i < D; i += 256) ts[i] = temb[b*D + i];
    __syncthreads();
    float acc = bias[j];
    const float* wp = w + j;
#pragma unroll 4
    for (int k = 0; k < D; k++) acc += ts[k] * wp[(size_t)k * (6*D)];
    g_ada[b*6*D + j] = acc;
}

// ---------------- logmap0 + layernorm + modulation + clipnorm (tf32-rounded out) ----------------
__global__ __launch_bounds__(256) void k_prep(const float* __restrict__ P,
                                              int sh_off, int sc_off,
                                              float* __restrict__ out){
    __shared__ float sb[8];
    const float LC = atanhf(MAXT);
    int row = blockIdx.x, b = row >> 10;
    int t = threadIdx.x;
    const float* xr = P + (size_t)row * D;
    float x0[4];
#pragma unroll
    for (int i=0;i<4;i++) x0[i] = xr[t + i*256];
    float ss = 0.f;
#pragma unroll
    for (int i=0;i<4;i++) ss += x0[i]*x0[i];
    ss = blk_sum(ss, sb);
    float n  = fmaxf(sqrtf(ss), EPSF);
    float a  = fminf(fmaxf(n, EPSF), MAXT);
    float ls = atanhf(a) / n;
    float u[4];
#pragma unroll
    for (int i=0;i<4;i++) u[i] = x0[i]*ls;
    float m = blk_sum(u[0]+u[1]+u[2]+u[3], sb) * (1.0f/D);
    float vv = 0.f;
#pragma unroll
    for (int i=0;i<4;i++){ float d0 = u[i]-m; vv += d0*d0; }
    vv = blk_sum(vv, sb) * (1.0f/D);
    float inv = rsqrtf(vv + 1e-6f);
    const float* ad = g_ada + b*6*D;
    float v[4]; float s2 = 0.f;
#pragma unroll
    for (int i=0;i<4;i++){
        int d0 = t + i*256;
        float xn  = (u[i]-m)*inv;
        float val = xn * (1.0f + ad[sc_off + d0]) + ad[sh_off + d0];
        v[i] = val; s2 += val*val;
    }
    s2 = blk_sum(s2, sb);
    float nv = fmaxf(sqrtf(s2), EPSF);
    float cl = fminf(nv, LC) / nv;
#pragma unroll
    for (int i=0;i<4;i++) out[(size_t)row*D + t + i*256] = rnd_t(v[i]*cl);
}

// ---------------- beta-split to heads (q/k/v via blockIdx.y) ----------------
__global__ __launch_bounds__(256) void k_heads(const float* __restrict__ lin3,
                                               float* __restrict__ qkvt, float Rf){
    __shared__ float sb[8];
    const float LC = atanhf(MAXT);
    int row = blockIdx.x, b = row >> 10, s = row & 1023;
    const float* lin = lin3 + (size_t)blockIdx.y*NROWS*D;
    float* out = qkvt + (size_t)blockIdx.y*NROWS*D;
    int t = threadIdx.x, h = t >> 4, c = (t & 15) * 4;
    float4 z = *(const float4*)(lin + (size_t)row*D + h*HDIM + c);
    float ss = z.x*z.x + z.y*z.y + z.z*z.z + z.w*z.w;
    float tot = blk_sum(ss, sb);
    float n  = fmaxf(sqrtf(tot), EPSF);
    float s1 = fminf(n, LC)/n * Rf;
    float tx = z.x*s1, ty = z.y*s1, tz = z.z*s1, tw = z.w*s1;
    float hs = tx*tx + ty*ty + tz*tz + tw*tw;
#pragma unroll
    for (int o=1;o<16;o<<=1) hs += __shfl_xor_sync(0xffffffffu, hs, o);
    float nh = fmaxf(sqrtf(hs), EPSF);
    float s2 = fminf(nh, LC)/nh;
    float4 o4 = make_float4(rnd_t(tx*s2), rnd_t(ty*s2), rnd_t(tz*s2), rnd_t(tw*s2));
    *(float4*)(out + ((size_t)(b*NH + h)*SQ + s)*HDIM + c) = o4;
}

// ---------------- merge heads (tf32-rounded out) ----------------
__global__ __launch_bounds__(256) void k_merge(const float* __restrict__ att,
                                               float* __restrict__ out, float Rinv){
    __shared__ float sb[8];
    const float LC = atanhf(MAXT);
    int row = blockIdx.x, b = row >> 10, s = row & 1023;
    int t = threadIdx.x, h = t >> 4, c = (t & 15) * 4;
    float4 z = *(const float4*)(att + ((size_t)(b*NH + h)*SQ + s)*HDIM + c);
    float hs = z.x*z.x + z.y*z.y + z.z*z.z + z.w*z.w;
#pragma unroll
    for (int o=1;o<16;o<<=1) hs += __shfl_xor_sync(0xffffffffu, hs, o);
    float nh = fmaxf(sqrtf(hs), EPSF);
    float s2 = fminf(nh, LC)/nh * Rinv;
    float tx = z.x*s2, ty = z.y*s2, tz = z.z*s2, tw = z.w*s2;
    float tot = blk_sum(tx*tx + ty*ty + tz*tz + tw*tw, sb);
    float n  = fmaxf(sqrtf(tot), EPSF);
    float s3 = fminf(n, LC)/n;
    float4 o4 = make_float4(rnd_t(tx*s3), rnd_t(ty*s3), rnd_t(tz*s3), rnd_t(tw*s3));
    *(float4*)(out + (size_t)row*D + h*HDIM + c) = o4;
}

// ---------------- clipnorm over FF=4096 row (tf32-rounded out) ----------------
__global__ __launch_bounds__(256) void k_rownorm_ff(float* __restrict__ X){
    __shared__ float sb[8];
    const float LC = atanhf(MAXT);
    size_t base = (size_t)blockIdx.x * FFD;
    int t = threadIdx.x;
    float v[16]; float ss = 0.f;
#pragma unroll
    for (int i=0;i<16;i++){ v[i] = X[base + t + i*256]; ss += v[i]*v[i]; }
    ss = blk_sum(ss, sb);
    float n = fmaxf(sqrtf(ss), EPSF);
    float s1 = fminf(n, LC)/n;
#pragma unroll
    for (int i=0;i<16;i++) X[base + t + i*256] = rnd_t(v[i]*s1);
}

// ---------------- gate*clip, expmap0, mobius_add with residual ----------------
template<bool PREP>
__global__ __launch_bounds__(256) void k_resmix(const float* __restrict__ Z, int g_off,
                                                const float* __restrict__ res,
                                                float* __restrict__ out,
                                                int sh_off, int sc_off,
                                                float* __restrict__ tm){
    __shared__ float sb[8];
    const float LC = atanhf(MAXT);
    int row = blockIdx.x, b = row >> 10;
    int t = threadIdx.x;
    size_t base = (size_t)row * D;
    float z[4], r0[4], gg[4];
#pragma unroll
    for (int i=0;i<4;i++){
        int d0 = t + i*256;
        z[i]  = Z[base + d0];
        r0[i] = res[base + d0];
        gg[i] = g_ada[b*6*D + g_off + d0];
    }
    float ss = 0.f;
#pragma unroll
    for (int i=0;i<4;i++) ss += z[i]*z[i];
    ss = blk_sum(ss, sb);
    float n  = fmaxf(sqrtf(ss), EPSF);
    float s1 = fminf(n, LC)/n;
    float tt[4]; float st = 0.f;
#pragma unroll
    for (int i=0;i<4;i++){ tt[i] = gg[i]*(z[i]*s1); st += tt[i]*tt[i]; }
    st = blk_sum(st, sb);
    float nt  = fmaxf(sqrtf(st), EPSF);
    float ysc = tanhf(nt)/nt;
    float y[4];
#pragma unroll
    for (int i=0;i<4;i++) y[i] = tt[i]*ysc;
    float x2=0.f, y2=0.f, xy=0.f;
#pragma unroll
    for (int i=0;i<4;i++){ x2 += r0[i]*r0[i]; y2 += y[i]*y[i]; xy += r0[i]*y[i]; }
    x2 = blk_sum(x2, sb);
    y2 = blk_sum(y2, sb);
    xy = blk_sum(xy, sb);
    float den = fmaxf(1.0f + 2.0f*xy + x2*y2, EPSF);
    float ca  = 1.0f + 2.0f*xy + y2;
    float cb  = 1.0f - x2;
    float o[4];
#pragma unroll
    for (int i=0;i<4;i++){
        o[i] = (ca*r0[i] + cb*y[i]) / den;
        out[base + t + i*256] = o[i];
    }
    if (PREP){
        float ss2 = 0.f;
#pragma unroll
        for (int i=0;i<4;i++) ss2 += o[i]*o[i];
        ss2 = blk_sum(ss2, sb);
        float n2 = fmaxf(sqrtf(ss2), EPSF);
        float a2 = fminf(fmaxf(n2, EPSF), MAXT);
        float ls = atanhf(a2) / n2;
        float u[4];
#pragma unroll
        for (int i=0;i<4;i++) u[i] = o[i]*ls;
        float m = blk_sum(u[0]+u[1]+u[2]+u[3], sb) * (1.0f/D);
        float vv = 0.f;
#pragma unroll
        for (int i=0;i<4;i++){ float dd = u[i]-m; vv += dd*dd; }
        vv = blk_sum(vv, sb) * (1.0f/D);
        float inv = rsqrtf(vv + 1e-6f);
        const float* ad = g_ada + b*6*D;
        float v[4]; float s2 = 0.f;
#pragma unroll
        for (int i=0;i<4;i++){
            int d0 = t + i*256;
            float xn  = (u[i]-m)*inv;
            float val = xn * (1.0f + ad[sc_off + d0]) + ad[sh_off + d0];
            v[i] = val; s2 += val*val;
        }
        s2 = blk_sum(s2, sb);
        float nv = fmaxf(sqrtf(s2), EPSF);
        float cl = fminf(nv, LC) / nv;
#pragma unroll
        for (int i=0;i<4;i++) tm[base + t + i*256] = rnd_t(v[i]*cl);
    }
}

// ---------------- fused flash attention (tf32 mma, online softmax) ----------------
#define QK_STRIDE 68
#define V_STRIDE  72
__global__ __launch_bounds__(256) void k_fattn(const float* __restrict__ qt,
                                               const float* __restrict__ kt,
                                               const float* __restrict__ vt,
                                               float* __restrict__ att){
    extern __shared__ unsigned smem_u[];
    unsigned* Qs = smem_u;
    unsigned* Ks = smem_u + 128*QK_STRIDE;
    unsigned* Vs = smem_u + 2*128*QK_STRIDE;

    const int tid = threadIdx.x, lane = tid & 31, wid = tid >> 5;
    const int gid = lane >> 2, tg = lane & 3;
    const int bh = blockIdx.y, q0 = blockIdx.x * 128;
    const float* Qb = qt + ((size_t)bh*SQ + q0)*HDIM;
    const float* Kb = kt + (size_t)bh*SQ*HDIM;
    const float* Vb = vt + (size_t)bh*SQ*HDIM;

#pragma unroll
    for (int it=0; it<8; it++){
        int row = it*16 + (tid>>4);
        int c4  = (tid & 15)*4;
        float4 v = *(const float4*)(Qb + (size_t)row*HDIM + c4);
        *(uint4*)&Qs[row*QK_STRIDE + c4] = cvt4(v);
    }

    float oacc[8][4];
#pragma unroll
    for (int i=0;i<8;i++){ oacc[i][0]=0.f; oacc[i][1]=0.f; oacc[i][2]=0.f; oacc[i][3]=0.f; }
    float m0 = -1e30f, m1 = -1e30f, l0 = 0.f, l1 = 0.f;
    const int qr = wid*16 + gid;

    for (int j=0; j<SQ/128; j++){
        __syncthreads();
#pragma unroll
        for (int it=0; it<8; it++){
            int row = it*16 + (tid>>4);
            int c4  = (tid & 15)*4;
            const float* kp = Kb + (size_t)(j*128+row)*HDIM + c4;
            *(uint4*)&Ks[row*QK_STRIDE + c4] = cvt4(*(const float4*)kp);
            const float* vp = Vb + (size_t)(j*128+row)*HDIM + c4;
            int r8 = row & 7;
            int s  = (r8 & 1) ? 4 + (r8>>1) : (r8>>1);
            int pr = (row & ~7) | s;
            *(uint4*)&Vs[pr*V_STRIDE + c4] = cvt4(*(const float4*)vp);
        }
        __syncthreads();

        float sf[16][4];
#pragma unroll
        for (int nt=0; nt<16; nt++){ sf[nt][0]=0.f; sf[nt][1]=0.f; sf[nt][2]=0.f; sf[nt][3]=0.f; }
#pragma unroll
        for (int ks=0; ks<8; ks++){
            unsigned a[4];
            a[0] = Qs[(qr  )*QK_STRIDE + ks*8 + tg  ];
            a[1] = Qs[(qr+8)*QK_STRIDE + ks*8 + tg  ];
            a[2] = Qs[(qr  )*QK_STRIDE + ks*8 + tg+4];
            a[3] = Qs[(qr+8)*QK_STRIDE + ks*8 + tg+4];
#pragma unroll
            for (int nt=0; nt<16; nt++){
                unsigned b[2];
                b[0] = Ks[(nt*8+gid)*QK_STRIDE + ks*8 + tg  ];
                b[1] = Ks[(nt*8+gid)*QK_STRIDE + ks*8 + tg+4];
                mma_tf32(sf[nt], a, b);
            }
        }
        float mx0 = -1e30f, mx1 = -1e30f;
#pragma unroll
        for (int nt=0; nt<16; nt++){
            sf[nt][0] *= 0.125f; sf[nt][1] *= 0.125f;
            sf[nt][2] *= 0.125f; sf[nt][3] *= 0.125f;
            mx0 = fmaxf(mx0, fmaxf(sf[nt][0], sf[nt][1]));
            mx1 = fmaxf(mx1, fmaxf(sf[nt][2], sf[nt][3]));
        }
        mx0 = fmaxf(mx0, __shfl_xor_sync(0xffffffffu, mx0, 1));
        mx0 = fmaxf(mx0, __shfl_xor_sync(0xffffffffu, mx0, 2));
        mx1 = fmaxf(mx1, __shfl_xor_sync(0xffffffffu, mx1, 1));
        mx1 = fmaxf(mx1, __shfl_xor_sync(0xffffffffu, mx1, 2));
        float m0n = fmaxf(m0, mx0), m1n = fmaxf(m1, mx1);
        float sc0 = __expf(m0 - m0n), sc1 = __expf(m1 - m1n);
        m0 = m0n; m1 = m1n;
        float rs0 = 0.f, rs1 = 0.f;
        unsigned paf[16][4];
#pragma unroll
        for (int nt=0; nt<16; nt++){
            float p0 = __expf(sf[nt][0] - m0n);
            float p1 = __expf(sf[nt][1] - m0n);
            float p2 = __expf(sf[nt][2] - m1n);
            float p3 = __expf(sf[nt][3] - m1n);
            rs0 += p0 + p1; rs1 += p2 + p3;
            paf[nt][0] = f2t(p0); paf[nt][1] = f2t(p2);
            paf[nt][2] = f2t(p1); paf[nt][3] = f2t(p3);
        }
        rs0 += __shfl_xor_sync(0xffffffffu, rs0, 1);
        rs0 += __shfl_xor_sync(0xffffffffu, rs0, 2);
        rs1 += __shfl_xor_sync(0xffffffffu, rs1, 1);
        rs1 += __shfl_xor_sync(0xffffffffu, rs1, 2);
        l0 = l0*sc0 + rs0; l1 = l1*sc1 + rs1;
#pragma unroll
        for (int d0=0; d0<8; d0++){
            oacc[d0][0] *= sc0; oacc[d0][1] *= sc0;
            oacc[d0][2] *= sc1; oacc[d0][3] *= sc1;
        }
#pragma unroll
        for (int ks=0; ks<16; ks++){
#pragma unroll
            for (int d0=0; d0<8; d0++){
                unsigned b[2];
                b[0] = Vs[(ks*8 + tg  )*V_STRIDE + d0*8 + gid];
                b[1] = Vs[(ks*8 + tg+4)*V_STRIDE + d0*8 + gid];
                mma_tf32(oacc[d0], paf[ks], b);
            }
        }
    }
    float il0 = 1.f / l0, il1 = 1.f / l1;
    float* Ob = att + ((size_t)bh*SQ + q0)*HDIM;
#pragma unroll
    for (int d0=0; d0<8; d0++){
        int c = d0*8 + 2*tg;
        *(float2*)(Ob + (size_t)qr*HDIM + c)     = make_float2(oacc[d0][0]*il0, oacc[d0][1]*il0);
        *(float2*)(Ob + (size_t)(qr+8)*HDIM + c) = make_float2(oacc[d0][2]*il1, oacc[d0][3]*il1);
    }
}

// ---------------- TF32 GEMM: BK=32, 3-stage cp.async, ldmatrix A-frags ----------------
// A [M,K] row-major, B [K,N] row-major (both tf32-pre-rounded; mma truncation exact).
// Block 128x128, BK=32, 256 threads (8 warps 2x4, warp 64x32), 2 blocks/SM.
// A smem stride 36 (banks 4r: ldmatrix phases conflict-free), B stride 136.
#define STAGES 3
#define A_ST (128*36)
#define B_ST (32*136)
__global__ __launch_bounds__(256, 2) void k_mma(
    const float* __restrict__ A, const float* __restrict__ Bw, size_t strideB,
    const float* __restrict__ bz0, const float* __restrict__ bz1, const float* __restrict__ bz2,
    float* __restrict__ C, size_t strideC, int N, int K)
{
    extern __shared__ float sm_f[];
    float* As = sm_f;
    float* Bs = sm_f + STAGES*A_ST;
    const int tid = threadIdx.x, lane = tid & 31, wid = tid >> 5;
    const int wm = wid >> 2, wn = wid & 3;
    const int gid = lane >> 2, tg = lane & 3;
    const int z = blockIdx.z;
    const float* Bb = Bw + (size_t)z*strideB;
    const float* bias = (z==0) ? bz0 : ((z==1) ? bz1 : bz2);
    float* Cb = C + (size_t)z*strideC;
    const int m0 = blockIdx.y * 128;
    const int n0 = blockIdx.x * 128;
    const int KT = K >> 5;

    const unsigned sA = (unsigned)__cvta_generic_to_shared(As);
    // ldmatrix x4 lane address: rows wm*64 + (lane&15), k-half (lane>>4)*4 floats
    const unsigned aoff = ((wm*64 + (lane & 15))*36 + (lane >> 4)*4) * 4;

    float acc[4][4][4];
#pragma unroll
    for (int i=0;i<4;i++)
#pragma unroll
        for (int j=0;j<4;j++)
#pragma unroll
            for (int r=0;r<4;r++) acc[i][j][r] = 0.f;

    auto issue = [&](int s, int kt){
        float* as = As + s*A_ST;
        float* bs = Bs + s*B_ST;
        int kb = kt << 5;
        // A tile: 128 rows x 32 floats (1024 16B chunks)
#pragma unroll
        for (int it=0; it<4; it++){
            int idx = it*256 + tid;
            int row = idx >> 3, c4 = (idx & 7)*4;
            cp16(&as[row*36 + c4], A + (size_t)(m0+row)*K + kb + c4);
        }
        // B tile: 32 rows x 128 floats
#pragma unroll
        for (int it=0; it<4; it++){
            int idx = it*256 + tid;
            int row = idx >> 5, c4 = (idx & 31)*4;
            cp16(&bs[row*136 + c4], Bb + (size_t)(kb+row)*N + n0 + c4);
        }
        asm volatile("cp.async.commit_group;");
    };

    auto comp = [&](int s){
        unsigned abase = sA + s*(A_ST*4) + aoff;
        const float* bs = Bs + s*B_ST;
#pragma unroll
        for (int ks=0; ks<32; ks+=8){
            unsigned af[4][4], bf[4][2];
#pragma unroll
            for (int im=0; im<4; im++)
                ldsm4(abase + (im*16*36 + ks)*4,
                      af[im][0], af[im][1], af[im][2], af[im][3]);
#pragma unroll
            for (int in=0; in<4; in++){
                int nc = wn*32 + in*8 + gid;
                bf[in][0] = __float_as_uint(bs[(ks+tg  )*136 + nc]);
                bf[in][1] = __float_as_uint(bs[(ks+tg+4)*136 + nc]);
            }
#pragma unroll
            for (int im=0; im<4; im++)
#pragma unroll
                for (int in=0; in<4; in++)
                    mma_tf32(acc[im][in], af[im], bf[in]);
        }
    };

    issue(0, 0);
    issue(1, 1);
    int sc = 0, si = 2;
    for (int kt=0; kt<KT; kt++){
        if (kt + 2 < KT){
            asm volatile("cp.async.wait_group 1;");
            __syncthreads();
            issue(si, kt+2);
            si = (si==2) ? 0 : si+1;
        } else {
            asm volatile("cp.async.wait_group 0;");   // exact drain on tail
            __syncthreads();
        }
        comp(sc);
        sc = (sc==2) ? 0 : sc+1;
        __syncthreads();   // stage sc fully consumed before another issue overwrites
    }

    // epilogue: C layout c0=(r,2tg) c1=(r,2tg+1) c2=(r+8,2tg) c3=(r+8,2tg+1)
#pragma unroll
    for (int im=0; im<4; im++){
        int r0 = m0 + wm*64 + im*16 + gid;
#pragma unroll
        for (int in=0; in<4; in++){
            int c = n0 + wn*32 + in*8 + tg*2;
            float b0 = bias[c], b1 = bias[c+1];
            *(float2*)(Cb + (size_t)r0*N + c) =
                make_float2(acc[im][in][0] + b0, acc[im][in][1] + b1);
            *(float2*)(Cb + (size_t)(r0+8)*N + c) =
                make_float2(acc[im][in][2] + b0, acc[im][in][3] + b1);
        }
    }
}

// ---------------- host launch ----------------
extern "C" void kernel_launch(void* const* d_in, const int* in_sizes, int n_in,
                              void* d_out, int out_size){
    (void)in_sizes; (void)n_in; (void)out_size;
    const float* x     = (const float*)d_in[0];
    const float* temb  = (const float*)d_in[1];
    const float* w_q   = (const float*)d_in[2];
    const float* b_q   = (const float*)d_in[3];
    const float* w_k   = (const float*)d_in[4];
    const float* b_k   = (const float*)d_in[5];
    const float* w_v   = (const float*)d_in[6];
    const float* b_v   = (const float*)d_in[7];
    const float* w_o   = (const float*)d_in[8];
    const float* b_o   = (const float*)d_in[9];
    const float* w_f1  = (const float*)d_in[10];
    const float* b_f1  = (const float*)d_in[11];
    const float* w_f2  = (const float*)d_in[12];
    const float* b_f2  = (const float*)d_in[13];
    const float* w_ada = (const float*)d_in[14];
    const float* b_ada = (const float*)d_in[15];
    float* out = (float*)d_out;

    float *tm, *lin3, *qkvt, *att, *tcat, *zb, *xnew, *big, *wbuf;
    cudaGetSymbolAddress((void**)&tm,   g_tm);
    cudaGetSymbolAddress((void**)&lin3, g_lin3);
    cudaGetSymbolAddress((void**)&qkvt, g_qkvt);
    cudaGetSymbolAddress((void**)&att,  g_att);
    cudaGetSymbolAddress((void**)&tcat, g_tcat);
    cudaGetSymbolAddress((void**)&zb,   g_zb);
    cudaGetSymbolAddress((void**)&xnew, g_xnew);
    cudaGetSymbolAddress((void**)&big,  g_big);
    cudaGetSymbolAddress((void**)&wbuf, g_w);

    double lgn = lgamma(512.0) + lgamma(0.5) - lgamma(512.5);
    double lgh = lgamma(32.0)  + lgamma(0.5) - lgamma(32.5);
    double betaN = exp(lgn), betaH = exp(lgh);
    float R    = (float)(betaH / betaN);
    float Rinv = (float)(betaN / betaH);

    const int fa_smem  = (2*128*QK_STRIDE + 128*V_STRIDE) * 4;
    const int mma_smem = STAGES*(A_ST + B_ST)*4;
    cudaFuncSetAttribute(k_fattn, cudaFuncAttributeMaxDynamicSharedMemorySize, fa_smem);
    cudaFuncSetAttribute(k_mma,   cudaFuncAttributeMaxDynamicSharedMemorySize, mma_smem);

    const size_t ND = (size_t)NROWS*D;

    // round all weights to tf32 (RN) into g_w: [q|k|v|o|f1|f2], layout [K,N]
    k_round6<<<dim3(4096,6,1),256>>>(w_q, w_k, w_v, w_o, w_f1, w_f2, wbuf);

    // ada
    k_ada<<<dim3(24,4,1), 256>>>(temb, w_ada, b_ada);

    // ---- attention block ----
    k_prep<<<NROWS, 256>>>(x, /*sh*/0, /*sc*/D, tm);

    // QKV fused over blockIdx.z
    k_mma<<<dim3(8,32,3),256,mma_smem>>>(tm, wbuf, WSZ, b_q, b_k, b_v,
                                         lin3, ND, 1024, 1024);
    k_heads<<<dim3(NROWS,3,1),256>>>(lin3, qkvt, R);

    k_fattn<<<dim3(SQ/128, BB*NH), 256, fa_smem>>>(qkvt, qkvt+ND, qkvt+2*ND, att);

    k_merge<<<NROWS,256>>>(att, tcat, Rinv);
    k_mma<<<dim3(8,32,1),256,mma_smem>>>(tcat, wbuf+3*WSZ, 0, b_o, b_o, b_o,
                                         zb, 0, 1024, 1024);
    k_resmix<true><<<NROWS,256>>>(zb, /*gate*/2*D, x, xnew, /*sh*/3*D, /*sc*/4*D, tm);

    // ---- FFN block ----
    k_mma<<<dim3(32,32,1),256,mma_smem>>>(tm, wbuf+4*WSZ, 0, b_f1, b_f1, b_f1,
                                          big, 0, 4096, 1024);
    k_rownorm_ff<<<NROWS,256>>>(big);
    k_mma<<<dim3(8,32,1),256,mma_smem>>>(big, wbuf+8*WSZ, 0, b_f2, b_f2, b_f2,
                                         zb, 0, 1024, 4096);
    k_resmix<false><<<NROWS,256>>>(zb, /*gate*/5*D, xnew, out, 0, 0, nullptr);
}